// round 13
// baseline (speedup 1.0000x reference)
#include <cuda_runtime.h>
#include <cuda_bf16.h>
#include <cstdint>

#define B_ 128
#define T_ 512
#define D_ 256
#define U_ 512
#define G4_ 2048
#define OUT_ 64
#define NL 64                     // lstm CTAs (1/SM, co-resident)

typedef unsigned int u32;

// ---- lstm smem layout (bytes) ----
#define LR     0                  // R resident: 2 terms x 32 rows x 1040B
#define LRT    33280
#define LA     66560              // A bufs: [2 buf][2 term] x (128 rows x 272B)
#define LA_T   34816
#define LA_BUF 69632
#define LD_    205824             // sD: 128 x 34 f32
#define LBE    223232
#define LBR    223360
#define L_TOT  223488

// ---- xproj smem layout ----
#define XB_TERM  33792            // 64 n-rows x 528B
#define XS_B     0
#define XA_ONE   17408
#define XS_A     67584
#define XS_D     137216           // 128 x 65 f32
#define XS_TOT   170496

__device__ float g_xproj[(size_t)T_ * G4_ * B_];          // [t][pcol][b]
__device__ float g_hall[(size_t)B_ * T_ * U_];            // [b][t][u]
__device__ __nv_bfloat16 g_Rhi[(size_t)G4_ * U_];         // [pcol][k]
__device__ __nv_bfloat16 g_Rlo[(size_t)G4_ * U_];
__device__ __nv_bfloat16 g_hKhi[2][U_ * B_];              // [k][m] ping-pong
__device__ __nv_bfloat16 g_hKlo[2][U_ * B_];
__device__ __nv_bfloat16 g_xhi[(size_t)T_ * D_ * B_];     // [t][d][b]
__device__ __nv_bfloat16 g_xlo[(size_t)T_ * D_ * B_];
__device__ __nv_bfloat16 g_Khi[(size_t)G4_ * D_];         // [pcol][d]
__device__ __nv_bfloat16 g_Klo[(size_t)G4_ * D_];
__device__ float g_be2[G4_], g_braw2[G4_];
__device__ unsigned g_step[NL];                           // per-CTA step flags

__device__ __forceinline__ float sigm(float x) { return __fdividef(1.f, 1.f + __expf(-x)); }
__device__ __forceinline__ float tanh_(float x) {
    float a = fabsf(x), e = __expf(-2.f * a);
    return copysignf(__fdividef(1.f - e, 1.f + e), x);
}
__device__ __forceinline__ void cpasync16(u32 s, const void *g) {
    asm volatile("cp.async.cg.shared.global [%0], [%1], 16;" :: "r"(s), "l"(g));
}
__device__ __forceinline__ void cpcommit() { asm volatile("cp.async.commit_group;"); }
__device__ __forceinline__ void cpwait0()  { asm volatile("cp.async.wait_group 0;"); }
__device__ __forceinline__ void cpwait1()  { asm volatile("cp.async.wait_group 1;"); }

#define LDSM4(r, a) asm volatile( \
    "ldmatrix.sync.aligned.m8n8.x4.shared.b16 {%0,%1,%2,%3}, [%4];" \
    : "=r"((r)[0]), "=r"((r)[1]), "=r"((r)[2]), "=r"((r)[3]) : "r"(a))
#define LDSM4T(r, a) asm volatile( \
    "ldmatrix.sync.aligned.m8n8.x4.trans.shared.b16 {%0,%1,%2,%3}, [%4];" \
    : "=r"((r)[0]), "=r"((r)[1]), "=r"((r)[2]), "=r"((r)[3]) : "r"(a))
#define MMA(d, a, b) asm volatile( \
    "mma.sync.aligned.m16n8k16.row.col.f32.bf16.bf16.f32 " \
    "{%0,%1,%2,%3}, {%4,%5,%6,%7}, {%8,%9}, {%0,%1,%2,%3};" \
    : "+f"((d)[0]), "+f"((d)[1]), "+f"((d)[2]), "+f"((d)[3]) \
    : "r"((a)[0]), "r"((a)[1]), "r"((a)[2]), "r"((a)[3]), "r"((b)[0]), "r"((b)[1]))

// pcol = (u>>3)*32 + (u&7)*4 + gate  (64 lstm blocks of 32 cols)
__device__ __forceinline__ int perm_col(int col) {
    int u = col & (U_ - 1), gate = col >> 9;
    return (u >> 3) * 32 + (u & 7) * 4 + gate;
}

// ---- prep kernels ----
__global__ void prep_reff_kernel(const float *__restrict__ wk,
                                 const float *__restrict__ rec,
                                 const float *__restrict__ dw) {
    int k = blockIdx.x, tid = threadIdx.x;
    __shared__ float dws[OUT_];
    if (tid < OUT_) dws[tid] = dw[k * OUT_ + tid];
    __syncthreads();
    for (int col = tid; col < G4_; col += 256) {
        float acc = rec[k * G4_ + col];
#pragma unroll 16
        for (int j = 0; j < OUT_; j++)
            acc += dws[j] * wk[(size_t)(D_ + j) * G4_ + col];
        size_t dst = (size_t)perm_col(col) * U_ + k;
        __nv_bfloat16 hi = __float2bfloat16(acc);
        g_Rhi[dst] = hi;
        g_Rlo[dst] = __float2bfloat16(acc - __bfloat162float(hi));
    }
}

__global__ void prep_bias_kernel(const float *__restrict__ wk,
                                 const float *__restrict__ bias,
                                 const float *__restrict__ db) {
    int col = blockIdx.x * 256 + threadIdx.x;
    float acc = 0.f;
#pragma unroll 16
    for (int j = 0; j < OUT_; j++)
        acc += db[j] * wk[(size_t)(D_ + j) * G4_ + col];
    int pcol = perm_col(col);
    g_braw2[pcol] = bias[col];
    g_be2[pcol] = bias[col] + acc;
}

__global__ void cvt_k_kernel(const float *__restrict__ wk) {
    int d = blockIdx.x;
    for (int col = threadIdx.x; col < G4_; col += 256) {
        float v = wk[(size_t)d * G4_ + col];
        __nv_bfloat16 hi = __float2bfloat16(v);
        size_t dst = (size_t)perm_col(col) * D_ + d;
        g_Khi[dst] = hi;
        g_Klo[dst] = __float2bfloat16(v - __bfloat162float(hi));
    }
}

__global__ void __launch_bounds__(256) cvt_x_kernel(const float *__restrict__ inp) {
    __shared__ float sm[128 * 65];
    int t = blockIdx.x, d0 = blockIdx.y * 64;
    int tid = threadIdx.x;
#pragma unroll
    for (int i = 0; i < 32; i++) {
        int idx = tid + i * 256;
        int b = idx >> 6, dl = idx & 63;
        sm[b * 65 + dl] = inp[((size_t)b * T_ + t) * D_ + d0 + dl];
    }
    __syncthreads();
#pragma unroll
    for (int i = 0; i < 32; i++) {
        int idx = tid + i * 256;
        int dl = idx >> 7, b = idx & 127;
        float v = sm[b * 65 + dl];
        __nv_bfloat16 hi = __float2bfloat16(v);
        size_t o = ((size_t)t * D_ + d0 + dl) * B_ + b;
        g_xhi[o] = hi;
        g_xlo[o] = __float2bfloat16(v - __bfloat162float(hi));
    }
}

__global__ void zero_flags_kernel() {
    if (threadIdx.x < NL) g_step[threadIdx.x] = 0;
}

// ---- Xproj on mma.sync bf16 hi/lo (validated R9, unchanged) ----
__global__ void __launch_bounds__(128, 1) xproj_mma() {
    extern __shared__ char smraw[];
    u32 sb = (u32)__cvta_generic_to_shared(smraw);
    float *sD = (float *)(smraw + XS_D);
    int tid = threadIdx.x, w = tid >> 5, l = tid & 31;
    int cb = blockIdx.x;
    int tbase = blockIdx.y * 2;

    {
        const char *kh = (const char *)g_Khi;
        const char *kl = (const char *)g_Klo;
#pragma unroll
        for (int i = 0; i < 16; i++) {
            int idx = tid + i * 128;
            int gr = idx >> 5, gc = idx & 31;
            u32 dsto = (u32)(gr * 528 + gc * 16);
            size_t srco = (((size_t)cb * 64 + gr) << 9) + gc * 16;
            cpasync16(sb + XS_B + dsto, kh + srco);
            cpasync16(sb + XS_B + XB_TERM + dsto, kl + srco);
        }
        const char *xh = (const char *)g_xhi;
        const char *xl = (const char *)g_xlo;
#pragma unroll
        for (int i = 0; i < 8; i++) {
            int idx = tid + i * 128;
            u32 so = (idx >> 4) * 272 + (idx & 15) * 16;
            size_t srco = (((size_t)tbase * D_ + (idx >> 4)) << 8) + (idx & 15) * 16;
            cpasync16(sb + XS_A + 0 * XA_ONE + so, xh + srco);
            cpasync16(sb + XS_A + 1 * XA_ONE + so, xl + srco);
        }
        cpcommit();
    }

    int a_row = ((l & 16) ? 8 : 0) + (l & 7);
    int a_mc  = w * 32 + ((l & 8) ? 8 : 0);
    int b_off = (((l & 16) ? 8 : 0) + (l & 7)) * 528 + ((l & 8) ? 16 : 0);

    float acc[2][8][4];
#pragma unroll
    for (int i = 0; i < 2; i++)
#pragma unroll
        for (int n8 = 0; n8 < 8; n8++)
#pragma unroll
            for (int j = 0; j < 4; j++) acc[i][n8][j] = 0.f;

    for (int cc = 0; cc < 8; cc++) {
        int buf = cc & 1;
        __syncthreads();
        if (cc < 7) {
            int nb = buf ^ 1;
            int tn = tbase + ((cc + 1) >> 2);
            int kcn = (cc + 1) & 3;
            const char *xh = (const char *)g_xhi;
            const char *xl = (const char *)g_xlo;
#pragma unroll
            for (int i = 0; i < 8; i++) {
                int idx = tid + i * 128;
                u32 so = (idx >> 4) * 272 + (idx & 15) * 16;
                size_t srco =
                    (((size_t)tn * D_ + kcn * 64 + (idx >> 4)) << 8) + (idx & 15) * 16;
                cpasync16(sb + XS_A + (nb * 2 + 0) * XA_ONE + so, xh + srco);
                cpasync16(sb + XS_A + (nb * 2 + 1) * XA_ONE + so, xl + srco);
            }
            cpcommit(); cpwait1();
        } else {
            cpwait0();
        }
        __syncthreads();

        int kc = cc & 3;
        u32 ahb = sb + XS_A + (buf * 2 + 0) * XA_ONE;
        u32 alb = sb + XS_A + (buf * 2 + 1) * XA_ONE;
#pragma unroll
        for (int kt = 0; kt < 4; kt++) {
            u32 bh[4][4], bl[4][4];
#pragma unroll
            for (int ng = 0; ng < 4; ng++) {
                u32 ba = sb + XS_B + (u32)(ng * (16 * 528)) + b_off
                       + (u32)kc * 128 + kt * 32;
                LDSM4(bh[ng], ba);
                LDSM4(bl[ng], ba + XB_TERM);
            }
#pragma unroll
            for (int i = 0; i < 2; i++) {
                u32 ah[4], al[4];
                u32 aoff = (u32)((kt * 16 + a_row) * 272 + (a_mc + i * 16) * 2);
                LDSM4T(ah, ahb + aoff);
                LDSM4T(al, alb + aoff);
#pragma unroll
                for (int ng = 0; ng < 4; ng++)
#pragma unroll
                    for (int nt = 0; nt < 2; nt++) {
                        MMA(acc[i][ng * 2 + nt], ah, &bh[ng][nt * 2]);
                        MMA(acc[i][ng * 2 + nt], al, &bh[ng][nt * 2]);
                        MMA(acc[i][ng * 2 + nt], ah, &bl[ng][nt * 2]);
                    }
            }
        }

        if (kc == 3) {
            int tcur = tbase + (cc >> 2);
#pragma unroll
            for (int i = 0; i < 2; i++)
#pragma unroll
                for (int n8 = 0; n8 < 8; n8++) {
                    int r = w * 32 + i * 16 + (l >> 2);
                    int ccol = n8 * 8 + (l & 3) * 2;
                    sD[r * 65 + ccol] = acc[i][n8][0];
                    sD[r * 65 + ccol + 1] = acc[i][n8][1];
                    sD[(r + 8) * 65 + ccol] = acc[i][n8][2];
                    sD[(r + 8) * 65 + ccol + 1] = acc[i][n8][3];
                }
            __syncthreads();
            size_t obase = ((size_t)tcur * G4_ + (size_t)cb * 64) * B_;
#pragma unroll
            for (int i = 0; i < 64; i++) {
                int idx = tid + i * 128;
                int n = idx >> 7, b = idx & 127;
                g_xproj[obase + (size_t)n * B_ + b] = sD[b * 65 + n];
            }
            if (cc < 7) {
#pragma unroll
                for (int i = 0; i < 2; i++)
#pragma unroll
                    for (int n8 = 0; n8 < 8; n8++)
#pragma unroll
                        for (int j = 0; j < 4; j++) acc[i][n8][j] = 0.f;
            }
        }
    }
}

// ---- persistent recurrence: 64 CTAs x 512 threads, 16 warps (m4 x n4) ----
__global__ void __launch_bounds__(512, 1) lstm_mma2() {
    extern __shared__ char smraw[];
    u32 sb = (u32)__cvta_generic_to_shared(smraw);
    int tid = threadIdx.x, w = tid >> 5, l = tid & 31;
    int wm = w & 3;              // m-split (m = wm*32..+31)
    int nq = w >> 2;             // n-octet (n = nq*8..+7)
    int cta = blockIdx.x;
    float *sD = (float *)(smraw + LD_);
    float *sbe = (float *)(smraw + LBE);
    float *sbr = (float *)(smraw + LBR);

    if (tid < 32) {
        sbe[tid] = g_be2[cta * 32 + tid];
        sbr[tid] = g_braw2[cta * 32 + tid];
    }
    // stage resident R (hi/lo): 32 rows x 1024B, smem pitch 1040
#pragma unroll
    for (int e = 0; e < 2; e++) {
        const char *src = (const char *)(e ? g_Rlo : g_Rhi) + (size_t)cta * 32 * U_ * 2;
#pragma unroll
        for (int i = 0; i < 4; i++) {
            int idx = tid + i * 512;
            int gr = idx >> 6, gc = idx & 63;
            cpasync16(sb + LR + e * LRT + gr * 1040 + gc * 16, src + (size_t)idx * 16);
        }
    }
    cpcommit(); cpwait0();
    __syncthreads();

    // fragment lane mappings (derived from validated R8/R11 formulas)
    int a_row = ((l & 16) ? 8 : 0) + (l & 7);
    int a_mc  = wm * 32 + ((l & 8) ? 8 : 0);
    int b_off = (nq * 8 + (l & 7)) * 1040 + (l >> 3) * 16;   // n8 rows x k32 span

    int b = tid & 127, q = tid >> 7;     // gate thread: batch b, unit-pair q
    float cst[2] = {0.f, 0.f};
    int ph = 0;

    for (int t = 0; t < T_; t++) {
        float xpf[8];
#pragma unroll
        for (int j = 0; j < 8; j++)
            xpf[j] = __ldcg(&g_xproj[((size_t)t * G4_ + cta * 32 + q * 8 + j) * B_ + b]);

        if (t) {
            const char *hhi = (const char *)g_hKhi[ph];
            const char *hlo = (const char *)g_hKlo[ph];
            float acc[2][4];
#pragma unroll
            for (int i = 0; i < 2; i++)
#pragma unroll
                for (int j = 0; j < 4; j++) acc[i][j] = 0.f;

            // stage chunk 0 -> buf 0 (chunk = 128 k-rows x 256B, both terms)
#pragma unroll
            for (int e = 0; e < 2; e++) {
                const char *s = e ? hlo : hhi;
#pragma unroll
                for (int i = 0; i < 4; i++) {
                    int idx = tid + i * 512;
                    u32 so = (idx >> 4) * 272 + (idx & 15) * 16;
                    cpasync16(sb + LA + e * LA_T + so, s + (size_t)idx * 16);
                }
            }
            cpcommit();

            for (int ch = 0; ch < 4; ch++) {
                int buf = ch & 1;
                __syncthreads();
                if (ch < 3) {
                    int nb = buf ^ 1;
#pragma unroll
                    for (int e = 0; e < 2; e++) {
                        const char *s = (e ? hlo : hhi) + (size_t)(ch + 1) * 32768;
#pragma unroll
                        for (int i = 0; i < 4; i++) {
                            int idx = tid + i * 512;
                            u32 so = (idx >> 4) * 272 + (idx & 15) * 16;
                            cpasync16(sb + LA + nb * LA_BUF + e * LA_T + so,
                                      s + (size_t)idx * 16);
                        }
                    }
                    cpcommit(); cpwait1();
                } else {
                    cpwait0();
                }
                __syncthreads();

                u32 ahb = sb + LA + buf * LA_BUF;
                u32 alb = ahb + LA_T;
#pragma unroll
                for (int kt = 0; kt < 4; kt++) {      // k32 per iter
                    u32 bh[4], bl[4];
                    u32 ba = sb + LR + b_off + (u32)ch * 256 + kt * 64;
                    LDSM4(bh, ba);
                    LDSM4(bl, ba + LRT);
#pragma unroll
                    for (int i = 0; i < 2; i++) {
#pragma unroll
                        for (int kf = 0; kf < 2; kf++) {
                            u32 ah[4], al[4];
                            u32 aoff = (u32)((kt * 32 + kf * 16 + a_row) * 272
                                             + (a_mc + i * 16) * 2);
                            LDSM4T(ah, ahb + aoff);
                            LDSM4T(al, alb + aoff);
                            MMA(acc[i], ah, &bh[kf * 2]);
                            MMA(acc[i], al, &bh[kf * 2]);
                            MMA(acc[i], ah, &bl[kf * 2]);
                        }
                    }
                }
            }
            // epilogue: partials (disjoint by n-octet)
#pragma unroll
            for (int i = 0; i < 2; i++) {
                int r = wm * 32 + i * 16 + (l >> 2);
                int cc = nq * 8 + (l & 3) * 2;
                *(float2 *)&sD[r * 34 + cc] = make_float2(acc[i][0], acc[i][1]);
                *(float2 *)&sD[(r + 8) * 34 + cc] = make_float2(acc[i][2], acc[i][3]);
            }
        }
        __syncthreads();

        {   // gates: all 512 threads, (b, q) -> units 2q, 2q+1
            float z[8];
            if (t) {
#pragma unroll
                for (int j = 0; j < 8; j++)
                    z[j] = sD[b * 34 + q * 8 + j] + xpf[j] + sbe[q * 8 + j];
            } else {
#pragma unroll
                for (int j = 0; j < 8; j++) z[j] = xpf[j] + sbr[q * 8 + j];
            }
            float hh[2];
#pragma unroll
            for (int u2 = 0; u2 < 2; u2++) {
                float zi = z[u2 * 4 + 0], zf = z[u2 * 4 + 1];
                float zg = z[u2 * 4 + 2], zo = z[u2 * 4 + 3];
                float cn = sigm(zf) * cst[u2] + sigm(zi) * tanh_(zg);
                cst[u2] = cn;
                hh[u2] = sigm(zo) * tanh_(cn);
            }
            int nxt = ph ^ 1;
#pragma unroll
            for (int u2 = 0; u2 < 2; u2++) {
                int ul = q * 2 + u2;
                __nv_bfloat16 hi = __float2bfloat16(hh[u2]);
                __nv_bfloat16 lo = __float2bfloat16(hh[u2] - __bfloat162float(hi));
                g_hKhi[nxt][(cta * 8 + ul) * B_ + b] = hi;
                g_hKlo[nxt][(cta * 8 + ul) * B_ + b] = lo;
            }
            float *d = &g_hall[((size_t)b * T_ + t) * U_ + cta * 8 + q * 2];
            *(float2 *)d = make_float2(hh[0], hh[1]);
        }
        __threadfence();
        __syncthreads();
        // O(1)-arrival flag barrier (proven R11)
        if (tid == 0) atomicExch(&g_step[cta], (unsigned)(t + 1));
        if (tid < NL) {
            while (*((volatile unsigned *)&g_step[tid]) < (unsigned)(t + 1)) { }
        }
        __syncthreads();
        ph ^= 1;
    }
}

// ---- dense head: Y = H @ dense_w + db ----
__global__ void __launch_bounds__(512) dense_kernel(const float *__restrict__ dw,
                                                    const float *__restrict__ db,
                                                    float *__restrict__ out) {
    __shared__ float sdw[128 * 64];
    __shared__ float sh[16 * 128];
    int tid = threadIdx.x;
    size_t r0 = (size_t)blockIdx.x * 16;
    int o = tid & 63, rr = tid >> 6;
    float a0 = 0.f, a1 = 0.f;
    for (int u0 = 0; u0 < 512; u0 += 128) {
        __syncthreads();
        for (int i = tid; i < 128 * 64; i += 512)
            sdw[i] = dw[(u0 + (i >> 6)) * 64 + (i & 63)];
        for (int i = tid; i < 16 * 128; i += 512)
            sh[i] = g_hall[(r0 + (i >> 7)) * 512 + u0 + (i & 127)];
        __syncthreads();
#pragma unroll 8
        for (int u = 0; u < 128; u++) {
            float wv = sdw[u * 64 + o];
            a0 = fmaf(sh[rr * 128 + u], wv, a0);
            a1 = fmaf(sh[(rr + 8) * 128 + u], wv, a1);
        }
    }
    float bo = db[o];
    out[(r0 + rr) * 64 + o] = a0 + bo;
    out[(r0 + rr + 8) * 64 + o] = a1 + bo;
}

// ---- launch ----
extern "C" void kernel_launch(void *const *d_in, const int *in_sizes, int n_in,
                              void *d_out, int out_size) {
    const float *inputs  = (const float *)d_in[0];
    const float *kernelw = (const float *)d_in[1];
    const float *rec     = (const float *)d_in[2];
    const float *bias    = (const float *)d_in[3];
    const float *dense_w = (const float *)d_in[4];
    const float *dense_b = (const float *)d_in[5];
    float *out = (float *)d_out;
    (void)in_sizes; (void)n_in; (void)out_size;

    cudaFuncSetAttribute(xproj_mma, cudaFuncAttributeMaxDynamicSharedMemorySize, XS_TOT);
    cudaFuncSetAttribute(lstm_mma2, cudaFuncAttributeMaxDynamicSharedMemorySize, L_TOT);

    cvt_k_kernel<<<D_, 256>>>(kernelw);
    cvt_x_kernel<<<dim3(T_, 4), 256>>>(inputs);
    prep_reff_kernel<<<U_, 256>>>(kernelw, rec, dense_w);
    prep_bias_kernel<<<G4_ / 256, 256>>>(kernelw, bias, dense_b);
    zero_flags_kernel<<<1, 64>>>();
    xproj_mma<<<dim3(32, T_ / 2), 128, XS_TOT>>>();
    lstm_mma2<<<NL, 512, L_TOT>>>();
    dense_kernel<<<(B_ * T_) / 16, 512>>>(dense_w, dense_b, out);
}

// round 14
// speedup vs baseline: 1.6798x; 1.6798x over previous
#include <cuda_runtime.h>
#include <cuda_bf16.h>
#include <cstdint>

#define B_ 128
#define T_ 512
#define D_ 256
#define U_ 512
#define G4_ 2048
#define OUT_ 64
#define NL 64                     // lstm CTAs (1/SM, co-resident)

typedef unsigned int u32;

// ---- lstm smem layout (bytes) ----
#define LR     0                  // R resident: 2 terms x 32 rows x 1040B
#define LRT    33280
#define LA     66560              // A bufs: [2 buf] x (128 rows x 272B), hi only
#define LA_BUF 34816
#define LD_    136192             // sD: 128 x 34 f32
#define LBE    153600
#define LBR    153728
#define L_TOT  153856

// ---- xproj smem layout ----
#define XB_TERM  33792            // 64 n-rows x 528B
#define XS_B     0
#define XA_ONE   17408
#define XS_A     67584
#define XS_D     137216           // 128 x 65 f32
#define XS_TOT   170496

__device__ float g_xproj[(size_t)T_ * G4_ * B_];          // [t][pcol][b]
__device__ float g_hall[(size_t)B_ * T_ * U_];            // [b][t][u]
__device__ __nv_bfloat16 g_Rhi[(size_t)G4_ * U_];         // [pcol][k]
__device__ __nv_bfloat16 g_Rlo[(size_t)G4_ * U_];
__device__ __nv_bfloat16 g_hKhi[2][U_ * B_];              // [k][m] ping-pong
__device__ __nv_bfloat16 g_xhi[(size_t)T_ * D_ * B_];     // [t][d][b]
__device__ __nv_bfloat16 g_xlo[(size_t)T_ * D_ * B_];
__device__ __nv_bfloat16 g_Khi[(size_t)G4_ * D_];         // [pcol][d]
__device__ __nv_bfloat16 g_Klo[(size_t)G4_ * D_];
__device__ float g_be2[G4_], g_braw2[G4_];
__device__ unsigned g_step[NL];                           // per-CTA step flags

__device__ __forceinline__ float sigm(float x) { return __fdividef(1.f, 1.f + __expf(-x)); }
__device__ __forceinline__ float tanh_(float x) {
    float a = fabsf(x), e = __expf(-2.f * a);
    return copysignf(__fdividef(1.f - e, 1.f + e), x);
}
__device__ __forceinline__ void cpasync16(u32 s, const void *g) {
    asm volatile("cp.async.cg.shared.global [%0], [%1], 16;" :: "r"(s), "l"(g));
}
__device__ __forceinline__ void cpcommit() { asm volatile("cp.async.commit_group;"); }
__device__ __forceinline__ void cpwait0()  { asm volatile("cp.async.wait_group 0;"); }
__device__ __forceinline__ void cpwait1()  { asm volatile("cp.async.wait_group 1;"); }

#define LDSM4(r, a) asm volatile( \
    "ldmatrix.sync.aligned.m8n8.x4.shared.b16 {%0,%1,%2,%3}, [%4];" \
    : "=r"((r)[0]), "=r"((r)[1]), "=r"((r)[2]), "=r"((r)[3]) : "r"(a))
#define LDSM4T(r, a) asm volatile( \
    "ldmatrix.sync.aligned.m8n8.x4.trans.shared.b16 {%0,%1,%2,%3}, [%4];" \
    : "=r"((r)[0]), "=r"((r)[1]), "=r"((r)[2]), "=r"((r)[3]) : "r"(a))
#define MMA(d, a, b) asm volatile( \
    "mma.sync.aligned.m16n8k16.row.col.f32.bf16.bf16.f32 " \
    "{%0,%1,%2,%3}, {%4,%5,%6,%7}, {%8,%9}, {%0,%1,%2,%3};" \
    : "+f"((d)[0]), "+f"((d)[1]), "+f"((d)[2]), "+f"((d)[3]) \
    : "r"((a)[0]), "r"((a)[1]), "r"((a)[2]), "r"((a)[3]), "r"((b)[0]), "r"((b)[1]))

// pcol = (u>>3)*32 + (u&7)*4 + gate  (64 lstm blocks of 32 cols)
__device__ __forceinline__ int perm_col(int col) {
    int u = col & (U_ - 1), gate = col >> 9;
    return (u >> 3) * 32 + (u & 7) * 4 + gate;
}

// ---- prep kernels ----
__global__ void prep_reff_kernel(const float *__restrict__ wk,
                                 const float *__restrict__ rec,
                                 const float *__restrict__ dw) {
    int k = blockIdx.x, tid = threadIdx.x;
    __shared__ float dws[OUT_];
    if (tid < OUT_) dws[tid] = dw[k * OUT_ + tid];
    __syncthreads();
    for (int col = tid; col < G4_; col += 256) {
        float acc = rec[k * G4_ + col];
#pragma unroll 16
        for (int j = 0; j < OUT_; j++)
            acc += dws[j] * wk[(size_t)(D_ + j) * G4_ + col];
        size_t dst = (size_t)perm_col(col) * U_ + k;
        __nv_bfloat16 hi = __float2bfloat16(acc);
        g_Rhi[dst] = hi;
        g_Rlo[dst] = __float2bfloat16(acc - __bfloat162float(hi));
    }
}

__global__ void prep_bias_kernel(const float *__restrict__ wk,
                                 const float *__restrict__ bias,
                                 const float *__restrict__ db) {
    int col = blockIdx.x * 256 + threadIdx.x;
    float acc = 0.f;
#pragma unroll 16
    for (int j = 0; j < OUT_; j++)
        acc += db[j] * wk[(size_t)(D_ + j) * G4_ + col];
    int pcol = perm_col(col);
    g_braw2[pcol] = bias[col];
    g_be2[pcol] = bias[col] + acc;
}

__global__ void cvt_k_kernel(const float *__restrict__ wk) {
    int d = blockIdx.x;
    for (int col = threadIdx.x; col < G4_; col += 256) {
        float v = wk[(size_t)d * G4_ + col];
        __nv_bfloat16 hi = __float2bfloat16(v);
        size_t dst = (size_t)perm_col(col) * D_ + d;
        g_Khi[dst] = hi;
        g_Klo[dst] = __float2bfloat16(v - __bfloat162float(hi));
    }
}

__global__ void __launch_bounds__(256) cvt_x_kernel(const float *__restrict__ inp) {
    __shared__ float sm[128 * 65];
    int t = blockIdx.x, d0 = blockIdx.y * 64;
    int tid = threadIdx.x;
#pragma unroll
    for (int i = 0; i < 32; i++) {
        int idx = tid + i * 256;
        int b = idx >> 6, dl = idx & 63;
        sm[b * 65 + dl] = inp[((size_t)b * T_ + t) * D_ + d0 + dl];
    }
    __syncthreads();
#pragma unroll
    for (int i = 0; i < 32; i++) {
        int idx = tid + i * 256;
        int dl = idx >> 7, b = idx & 127;
        float v = sm[b * 65 + dl];
        __nv_bfloat16 hi = __float2bfloat16(v);
        size_t o = ((size_t)t * D_ + d0 + dl) * B_ + b;
        g_xhi[o] = hi;
        g_xlo[o] = __float2bfloat16(v - __bfloat162float(hi));
    }
}

__global__ void zero_flags_kernel() {
    if (threadIdx.x < NL) g_step[threadIdx.x] = 0;
}

// ---- Xproj on mma.sync bf16 hi/lo (validated R9, unchanged) ----
__global__ void __launch_bounds__(128, 1) xproj_mma() {
    extern __shared__ char smraw[];
    u32 sb = (u32)__cvta_generic_to_shared(smraw);
    float *sD = (float *)(smraw + XS_D);
    int tid = threadIdx.x, w = tid >> 5, l = tid & 31;
    int cb = blockIdx.x;
    int tbase = blockIdx.y * 2;

    {
        const char *kh = (const char *)g_Khi;
        const char *kl = (const char *)g_Klo;
#pragma unroll
        for (int i = 0; i < 16; i++) {
            int idx = tid + i * 128;
            int gr = idx >> 5, gc = idx & 31;
            u32 dsto = (u32)(gr * 528 + gc * 16);
            size_t srco = (((size_t)cb * 64 + gr) << 9) + gc * 16;
            cpasync16(sb + XS_B + dsto, kh + srco);
            cpasync16(sb + XS_B + XB_TERM + dsto, kl + srco);
        }
        const char *xh = (const char *)g_xhi;
        const char *xl = (const char *)g_xlo;
#pragma unroll
        for (int i = 0; i < 8; i++) {
            int idx = tid + i * 128;
            u32 so = (idx >> 4) * 272 + (idx & 15) * 16;
            size_t srco = (((size_t)tbase * D_ + (idx >> 4)) << 8) + (idx & 15) * 16;
            cpasync16(sb + XS_A + 0 * XA_ONE + so, xh + srco);
            cpasync16(sb + XS_A + 1 * XA_ONE + so, xl + srco);
        }
        cpcommit();
    }

    int a_row = ((l & 16) ? 8 : 0) + (l & 7);
    int a_mc  = w * 32 + ((l & 8) ? 8 : 0);
    int b_off = (((l & 16) ? 8 : 0) + (l & 7)) * 528 + ((l & 8) ? 16 : 0);

    float acc[2][8][4];
#pragma unroll
    for (int i = 0; i < 2; i++)
#pragma unroll
        for (int n8 = 0; n8 < 8; n8++)
#pragma unroll
            for (int j = 0; j < 4; j++) acc[i][n8][j] = 0.f;

    for (int cc = 0; cc < 8; cc++) {
        int buf = cc & 1;
        __syncthreads();
        if (cc < 7) {
            int nb = buf ^ 1;
            int tn = tbase + ((cc + 1) >> 2);
            int kcn = (cc + 1) & 3;
            const char *xh = (const char *)g_xhi;
            const char *xl = (const char *)g_xlo;
#pragma unroll
            for (int i = 0; i < 8; i++) {
                int idx = tid + i * 128;
                u32 so = (idx >> 4) * 272 + (idx & 15) * 16;
                size_t srco =
                    (((size_t)tn * D_ + kcn * 64 + (idx >> 4)) << 8) + (idx & 15) * 16;
                cpasync16(sb + XS_A + (nb * 2 + 0) * XA_ONE + so, xh + srco);
                cpasync16(sb + XS_A + (nb * 2 + 1) * XA_ONE + so, xl + srco);
            }
            cpcommit(); cpwait1();
        } else {
            cpwait0();
        }
        __syncthreads();

        int kc = cc & 3;
        u32 ahb = sb + XS_A + (buf * 2 + 0) * XA_ONE;
        u32 alb = sb + XS_A + (buf * 2 + 1) * XA_ONE;
#pragma unroll
        for (int kt = 0; kt < 4; kt++) {
            u32 bh[4][4], bl[4][4];
#pragma unroll
            for (int ng = 0; ng < 4; ng++) {
                u32 ba = sb + XS_B + (u32)(ng * (16 * 528)) + b_off
                       + (u32)kc * 128 + kt * 32;
                LDSM4(bh[ng], ba);
                LDSM4(bl[ng], ba + XB_TERM);
            }
#pragma unroll
            for (int i = 0; i < 2; i++) {
                u32 ah[4], al[4];
                u32 aoff = (u32)((kt * 16 + a_row) * 272 + (a_mc + i * 16) * 2);
                LDSM4T(ah, ahb + aoff);
                LDSM4T(al, alb + aoff);
#pragma unroll
                for (int ng = 0; ng < 4; ng++)
#pragma unroll
                    for (int nt = 0; nt < 2; nt++) {
                        MMA(acc[i][ng * 2 + nt], ah, &bh[ng][nt * 2]);
                        MMA(acc[i][ng * 2 + nt], al, &bh[ng][nt * 2]);
                        MMA(acc[i][ng * 2 + nt], ah, &bl[ng][nt * 2]);
                    }
            }
        }

        if (kc == 3) {
            int tcur = tbase + (cc >> 2);
#pragma unroll
            for (int i = 0; i < 2; i++)
#pragma unroll
                for (int n8 = 0; n8 < 8; n8++) {
                    int r = w * 32 + i * 16 + (l >> 2);
                    int ccol = n8 * 8 + (l & 3) * 2;
                    sD[r * 65 + ccol] = acc[i][n8][0];
                    sD[r * 65 + ccol + 1] = acc[i][n8][1];
                    sD[(r + 8) * 65 + ccol] = acc[i][n8][2];
                    sD[(r + 8) * 65 + ccol + 1] = acc[i][n8][3];
                }
            __syncthreads();
            size_t obase = ((size_t)tcur * G4_ + (size_t)cb * 64) * B_;
#pragma unroll
            for (int i = 0; i < 64; i++) {
                int idx = tid + i * 128;
                int n = idx >> 7, b = idx & 127;
                g_xproj[obase + (size_t)n * B_ + b] = sD[b * 65 + n];
            }
            if (cc < 7) {
#pragma unroll
                for (int i = 0; i < 2; i++)
#pragma unroll
                    for (int n8 = 0; n8 < 8; n8++)
#pragma unroll
                        for (int j = 0; j < 4; j++) acc[i][n8][j] = 0.f;
            }
        }
    }
}

// ---- persistent recurrence: R11 structure, h_lo term dropped ----
__global__ void __launch_bounds__(256, 1) lstm_mma2() {
    extern __shared__ char smraw[];
    u32 sb = (u32)__cvta_generic_to_shared(smraw);
    int tid = threadIdx.x, w = tid >> 5, l = tid & 31;
    int wm = w & 3;              // m-split (m = wm*32..+31)
    int nh = w >> 2;             // n-half (0/1)
    int cta = blockIdx.x;
    float *sD = (float *)(smraw + LD_);
    float *sbe = (float *)(smraw + LBE);
    float *sbr = (float *)(smraw + LBR);

    if (tid < 32) {
        sbe[tid] = g_be2[cta * 32 + tid];
        sbr[tid] = g_braw2[cta * 32 + tid];
    }
    // stage resident R (hi/lo): 32 rows x 1024B, smem pitch 1040
#pragma unroll
    for (int e = 0; e < 2; e++) {
        const char *src = (const char *)(e ? g_Rlo : g_Rhi) + (size_t)cta * 32 * U_ * 2;
#pragma unroll
        for (int i = 0; i < 8; i++) {
            int idx = tid + i * 256;
            int gr = idx >> 6, gc = idx & 63;
            cpasync16(sb + LR + e * LRT + gr * 1040 + gc * 16, src + (size_t)idx * 16);
        }
    }
    cpcommit(); cpwait0();
    __syncthreads();

    int a_row = ((l & 16) ? 8 : 0) + (l & 7);
    int a_mc  = wm * 32 + ((l & 8) ? 8 : 0);
    int b_off = (nh * 16 + ((l & 16) ? 8 : 0) + (l & 7)) * 1040 + ((l & 8) ? 16 : 0);

    float cst[8];
#pragma unroll
    for (int i = 0; i < 8; i++) cst[i] = 0.f;
    int ph = 0;

    for (int t = 0; t < T_; t++) {
        float xpf[32];
        if (tid < 128) {
#pragma unroll
            for (int n = 0; n < 32; n++)
                xpf[n] = __ldcg(&g_xproj[((size_t)t * G4_ + cta * 32 + n) * B_ + tid]);
        }

        if (t) {
            const char *hhi = (const char *)g_hKhi[ph];
            float acc[2][2][4];
#pragma unroll
            for (int i = 0; i < 2; i++)
#pragma unroll
                for (int nt = 0; nt < 2; nt++)
#pragma unroll
                    for (int j = 0; j < 4; j++) acc[i][nt][j] = 0.f;

            // stage chunk 0 -> buf 0 (chunk = 128 k-rows x 256B, hi only)
#pragma unroll
            for (int i = 0; i < 8; i++) {
                int idx = tid + i * 256;
                u32 so = (idx >> 4) * 272 + (idx & 15) * 16;
                cpasync16(sb + LA + so, hhi + (size_t)idx * 16);
            }
            cpcommit();

            for (int ch = 0; ch < 4; ch++) {
                int buf = ch & 1;
                __syncthreads();
                if (ch < 3) {
                    int nb = buf ^ 1;
                    const char *s = hhi + (size_t)(ch + 1) * 32768;
#pragma unroll
                    for (int i = 0; i < 8; i++) {
                        int idx = tid + i * 256;
                        u32 so = (idx >> 4) * 272 + (idx & 15) * 16;
                        cpasync16(sb + LA + nb * LA_BUF + so, s + (size_t)idx * 16);
                    }
                    cpcommit(); cpwait1();
                } else {
                    cpwait0();
                }
                __syncthreads();

                u32 ahb = sb + LA + buf * LA_BUF;
#pragma unroll
                for (int kt = 0; kt < 8; kt++) {
                    u32 bh[4], bl[4];
                    u32 ba = sb + LR + b_off + (u32)ch * 256 + kt * 32;
                    LDSM4(bh, ba);
                    LDSM4(bl, ba + LRT);
#pragma unroll
                    for (int i = 0; i < 2; i++) {
                        u32 ah[4];
                        u32 aoff = (u32)((kt * 16 + a_row) * 272 + (a_mc + i * 16) * 2);
                        LDSM4T(ah, ahb + aoff);
#pragma unroll
                        for (int nt = 0; nt < 2; nt++) {
                            MMA(acc[i][nt], ah, &bh[nt * 2]);
                            MMA(acc[i][nt], ah, &bl[nt * 2]);
                        }
                    }
                }
            }
            // epilogue: write partials (disjoint by n-half)
#pragma unroll
            for (int i = 0; i < 2; i++)
#pragma unroll
                for (int nt = 0; nt < 2; nt++) {
                    int r = wm * 32 + i * 16 + (l >> 2);
                    int cc = nh * 16 + nt * 8 + (l & 3) * 2;
                    *(float2 *)&sD[r * 34 + cc] =
                        make_float2(acc[i][nt][0], acc[i][nt][1]);
                    *(float2 *)&sD[(r + 8) * 34 + cc] =
                        make_float2(acc[i][nt][2], acc[i][nt][3]);
                }
        }
        __syncthreads();

        if (tid < 128) {
            int b = tid;
            float z[32];
            if (t) {
#pragma unroll
                for (int n = 0; n < 32; n++) z[n] = sD[b * 34 + n] + xpf[n] + sbe[n];
            } else {
#pragma unroll
                for (int n = 0; n < 32; n++) z[n] = xpf[n] + sbr[n];
            }
            float hh[8];
#pragma unroll
            for (int ul = 0; ul < 8; ul++) {
                float zi = z[ul * 4 + 0], zf = z[ul * 4 + 1];
                float zg = z[ul * 4 + 2], zo = z[ul * 4 + 3];
                float cn = sigm(zf) * cst[ul] + sigm(zi) * tanh_(zg);
                cst[ul] = cn;
                hh[ul] = sigm(zo) * tanh_(cn);
            }
            {
                float *d = &g_hall[((size_t)b * T_ + t) * U_ + cta * 8];
                *(float4 *)(d + 0) = make_float4(hh[0], hh[1], hh[2], hh[3]);
                *(float4 *)(d + 4) = make_float4(hh[4], hh[5], hh[6], hh[7]);
            }
            int nxt = ph ^ 1;
#pragma unroll
            for (int ul = 0; ul < 8; ul++)
                g_hKhi[nxt][(cta * 8 + ul) * B_ + b] = __float2bfloat16(hh[ul]);
        }
        __syncthreads();
        // single-thread release + O(1)-arrival flag barrier
        if (tid == 0) {
            asm volatile("fence.release.gpu;" ::: "memory");
            asm volatile("st.relaxed.gpu.global.u32 [%0], %1;"
                         :: "l"(&g_step[cta]), "r"((unsigned)(t + 1)) : "memory");
        }
        if (tid < NL) {
            while (*((volatile unsigned *)&g_step[tid]) < (unsigned)(t + 1)) { }
        }
        __syncthreads();
        ph ^= 1;
    }
}

// ---- dense head: Y = H @ dense_w + db ----
__global__ void __launch_bounds__(512) dense_kernel(const float *__restrict__ dw,
                                                    const float *__restrict__ db,
                                                    float *__restrict__ out) {
    __shared__ float sdw[128 * 64];
    __shared__ float sh[16 * 128];
    int tid = threadIdx.x;
    size_t r0 = (size_t)blockIdx.x * 16;
    int o = tid & 63, rr = tid >> 6;
    float a0 = 0.f, a1 = 0.f;
    for (int u0 = 0; u0 < 512; u0 += 128) {
        __syncthreads();
        for (int i = tid; i < 128 * 64; i += 512)
            sdw[i] = dw[(u0 + (i >> 6)) * 64 + (i & 63)];
        for (int i = tid; i < 16 * 128; i += 512)
            sh[i] = g_hall[(r0 + (i >> 7)) * 512 + u0 + (i & 127)];
        __syncthreads();
#pragma unroll 8
        for (int u = 0; u < 128; u++) {
            float wv = sdw[u * 64 + o];
            a0 = fmaf(sh[rr * 128 + u], wv, a0);
            a1 = fmaf(sh[(rr + 8) * 128 + u], wv, a1);
        }
    }
    float bo = db[o];
    out[(r0 + rr) * 64 + o] = a0 + bo;
    out[(r0 + rr + 8) * 64 + o] = a1 + bo;
}

// ---- launch ----
extern "C" void kernel_launch(void *const *d_in, const int *in_sizes, int n_in,
                              void *d_out, int out_size) {
    const float *inputs  = (const float *)d_in[0];
    const float *kernelw = (const float *)d_in[1];
    const float *rec     = (const float *)d_in[2];
    const float *bias    = (const float *)d_in[3];
    const float *dense_w = (const float *)d_in[4];
    const float *dense_b = (const float *)d_in[5];
    float *out = (float *)d_out;
    (void)in_sizes; (void)n_in; (void)out_size;

    cudaFuncSetAttribute(xproj_mma, cudaFuncAttributeMaxDynamicSharedMemorySize, XS_TOT);
    cudaFuncSetAttribute(lstm_mma2, cudaFuncAttributeMaxDynamicSharedMemorySize, L_TOT);

    cvt_k_kernel<<<D_, 256>>>(kernelw);
    cvt_x_kernel<<<dim3(T_, 4), 256>>>(inputs);
    prep_reff_kernel<<<U_, 256>>>(kernelw, rec, dense_w);
    prep_bias_kernel<<<G4_ / 256, 256>>>(kernelw, bias, dense_b);
    zero_flags_kernel<<<1, 64>>>();
    xproj_mma<<<dim3(32, T_ / 2), 128, XS_TOT>>>();
    lstm_mma2<<<NL, 256, L_TOT>>>();
    dense_kernel<<<(B_ * T_) / 16, 512>>>(dense_w, dense_b, out);
}

// round 16
// speedup vs baseline: 1.8872x; 1.1235x over previous
#include <cuda_runtime.h>
#include <cuda_bf16.h>
#include <cstdint>

#define B_ 128
#define T_ 512
#define D_ 256
#define U_ 512
#define G4_ 2048
#define OUT_ 64
#define NL 64                     // lstm CTAs (1/SM, co-resident)

typedef unsigned int u32;

// ---- lstm smem layout (bytes) ----
#define LR     0                  // R resident: 2 terms x 32 rows x 1040B
#define LRT    33280
#define LA     66560              // A bufs: [2 buf][2 term] x (128 rows x 272B)
#define LA_T   34816
#define LA_BUF 69632
#define LD_    205824             // sD: 128 x 34 f32
#define LBE    223232
#define LBR    223360
#define L_TOT  223488

// ---- xproj smem layout ----
#define XB_TERM  33792            // 64 n-rows x 528B
#define XS_B     0
#define XA_ONE   17408
#define XS_A     67584
#define XS_D     137216           // 128 x 65 f32
#define XS_TOT   170496

#define XT_PER   16               // timesteps per xproj CTA (B tile amortized)

__device__ float g_xproj[(size_t)T_ * G4_ * B_];          // [t][pcol][b]
__device__ float g_hall[(size_t)B_ * T_ * U_];            // [b][t][u]
__device__ __nv_bfloat16 g_Rhi[(size_t)G4_ * U_];         // [pcol][k]
__device__ __nv_bfloat16 g_Rlo[(size_t)G4_ * U_];
__device__ __nv_bfloat16 g_hKhi[2][U_ * B_];              // [k][m] ping-pong
__device__ __nv_bfloat16 g_hKlo[2][U_ * B_];
__device__ __nv_bfloat16 g_xhi[(size_t)T_ * D_ * B_];     // [t][d][b]
__device__ __nv_bfloat16 g_xlo[(size_t)T_ * D_ * B_];
__device__ __nv_bfloat16 g_Khi[(size_t)G4_ * D_];         // [pcol][d]
__device__ __nv_bfloat16 g_Klo[(size_t)G4_ * D_];
__device__ float g_be2[G4_], g_braw2[G4_];
__device__ unsigned g_step[NL];                           // per-CTA step flags

__device__ __forceinline__ float sigm(float x) { return __fdividef(1.f, 1.f + __expf(-x)); }
__device__ __forceinline__ float tanh_(float x) {
    float a = fabsf(x), e = __expf(-2.f * a);
    return copysignf(__fdividef(1.f - e, 1.f + e), x);
}
__device__ __forceinline__ void cpasync16(u32 s, const void *g) {
    asm volatile("cp.async.cg.shared.global [%0], [%1], 16;" :: "r"(s), "l"(g));
}
__device__ __forceinline__ void cpcommit() { asm volatile("cp.async.commit_group;"); }
__device__ __forceinline__ void cpwait0()  { asm volatile("cp.async.wait_group 0;"); }
__device__ __forceinline__ void cpwait1()  { asm volatile("cp.async.wait_group 1;"); }

#define LDSM4(r, a) asm volatile( \
    "ldmatrix.sync.aligned.m8n8.x4.shared.b16 {%0,%1,%2,%3}, [%4];" \
    : "=r"((r)[0]), "=r"((r)[1]), "=r"((r)[2]), "=r"((r)[3]) : "r"(a))
#define LDSM4T(r, a) asm volatile( \
    "ldmatrix.sync.aligned.m8n8.x4.trans.shared.b16 {%0,%1,%2,%3}, [%4];" \
    : "=r"((r)[0]), "=r"((r)[1]), "=r"((r)[2]), "=r"((r)[3]) : "r"(a))
#define MMA(d, a, b) asm volatile( \
    "mma.sync.aligned.m16n8k16.row.col.f32.bf16.bf16.f32 " \
    "{%0,%1,%2,%3}, {%4,%5,%6,%7}, {%8,%9}, {%0,%1,%2,%3};" \
    : "+f"((d)[0]), "+f"((d)[1]), "+f"((d)[2]), "+f"((d)[3]) \
    : "r"((a)[0]), "r"((a)[1]), "r"((a)[2]), "r"((a)[3]), "r"((b)[0]), "r"((b)[1]))

// pcol = (u>>3)*32 + (u&7)*4 + gate  (64 lstm blocks of 32 cols)
__device__ __forceinline__ int perm_col(int col) {
    int u = col & (U_ - 1), gate = col >> 9;
    return (u >> 3) * 32 + (u & 7) * 4 + gate;
}

// ---- prep kernels ----
__global__ void prep_reff_kernel(const float *__restrict__ wk,
                                 const float *__restrict__ rec,
                                 const float *__restrict__ dw) {
    int k = blockIdx.x, tid = threadIdx.x;
    __shared__ float dws[OUT_];
    if (tid < OUT_) dws[tid] = dw[k * OUT_ + tid];
    __syncthreads();
    for (int col = tid; col < G4_; col += 256) {
        float acc = rec[k * G4_ + col];
#pragma unroll 16
        for (int j = 0; j < OUT_; j++)
            acc += dws[j] * wk[(size_t)(D_ + j) * G4_ + col];
        size_t dst = (size_t)perm_col(col) * U_ + k;
        __nv_bfloat16 hi = __float2bfloat16(acc);
        g_Rhi[dst] = hi;
        g_Rlo[dst] = __float2bfloat16(acc - __bfloat162float(hi));
    }
}

__global__ void prep_bias_kernel(const float *__restrict__ wk,
                                 const float *__restrict__ bias,
                                 const float *__restrict__ db) {
    int col = blockIdx.x * 256 + threadIdx.x;
    float acc = 0.f;
#pragma unroll 16
    for (int j = 0; j < OUT_; j++)
        acc += db[j] * wk[(size_t)(D_ + j) * G4_ + col];
    int pcol = perm_col(col);
    g_braw2[pcol] = bias[col];
    g_be2[pcol] = bias[col] + acc;
}

__global__ void cvt_k_kernel(const float *__restrict__ wk) {
    int d = blockIdx.x;
    for (int col = threadIdx.x; col < G4_; col += 256) {
        float v = wk[(size_t)d * G4_ + col];
        __nv_bfloat16 hi = __float2bfloat16(v);
        size_t dst = (size_t)perm_col(col) * D_ + d;
        g_Khi[dst] = hi;
        g_Klo[dst] = __float2bfloat16(v - __bfloat162float(hi));
    }
}

__global__ void __launch_bounds__(256) cvt_x_kernel(const float *__restrict__ inp) {
    __shared__ float sm[128 * 65];
    int t = blockIdx.x, d0 = blockIdx.y * 64;
    int tid = threadIdx.x;
#pragma unroll
    for (int i = 0; i < 32; i++) {
        int idx = tid + i * 256;
        int b = idx >> 6, dl = idx & 63;
        sm[b * 65 + dl] = inp[((size_t)b * T_ + t) * D_ + d0 + dl];
    }
    __syncthreads();
#pragma unroll
    for (int i = 0; i < 32; i++) {
        int idx = tid + i * 256;
        int dl = idx >> 7, b = idx & 127;
        float v = sm[b * 65 + dl];
        __nv_bfloat16 hi = __float2bfloat16(v);
        size_t o = ((size_t)t * D_ + d0 + dl) * B_ + b;
        g_xhi[o] = hi;
        g_xlo[o] = __float2bfloat16(v - __bfloat162float(hi));
    }
}

__global__ void zero_flags_kernel() {
    if (threadIdx.x < NL) g_step[threadIdx.x] = 0;
}

// ---- Xproj on mma.sync bf16 hi/lo: 16 t per CTA, B tile staged once ----
__global__ void __launch_bounds__(128, 1) xproj_mma() {
    extern __shared__ char smraw[];
    u32 sb = (u32)__cvta_generic_to_shared(smraw);
    float *sD = (float *)(smraw + XS_D);
    int tid = threadIdx.x, w = tid >> 5, l = tid & 31;
    int cb = blockIdx.x;
    int tbase = blockIdx.y * XT_PER;

    {   // prologue: stage B (weights, both terms) + A chunk0 of t0
        const char *kh = (const char *)g_Khi;
        const char *kl = (const char *)g_Klo;
#pragma unroll
        for (int i = 0; i < 16; i++) {
            int idx = tid + i * 128;
            int gr = idx >> 5, gc = idx & 31;
            u32 dsto = (u32)(gr * 528 + gc * 16);
            size_t srco = (((size_t)cb * 64 + gr) << 9) + gc * 16;
            cpasync16(sb + XS_B + dsto, kh + srco);
            cpasync16(sb + XS_B + XB_TERM + dsto, kl + srco);
        }
        const char *xh = (const char *)g_xhi;
        const char *xl = (const char *)g_xlo;
#pragma unroll
        for (int i = 0; i < 8; i++) {
            int idx = tid + i * 128;
            u32 so = (idx >> 4) * 272 + (idx & 15) * 16;
            size_t srco = (((size_t)tbase * D_ + (idx >> 4)) << 8) + (idx & 15) * 16;
            cpasync16(sb + XS_A + 0 * XA_ONE + so, xh + srco);
            cpasync16(sb + XS_A + 1 * XA_ONE + so, xl + srco);
        }
        cpcommit();
    }

    int a_row = ((l & 16) ? 8 : 0) + (l & 7);
    int a_mc  = w * 32 + ((l & 8) ? 8 : 0);
    int b_off = (((l & 16) ? 8 : 0) + (l & 7)) * 528 + ((l & 8) ? 16 : 0);

    float acc[2][8][4];
#pragma unroll
    for (int i = 0; i < 2; i++)
#pragma unroll
        for (int n8 = 0; n8 < 8; n8++)
#pragma unroll
            for (int j = 0; j < 4; j++) acc[i][n8][j] = 0.f;

    for (int cc = 0; cc < 4 * XT_PER; cc++) {     // 16 t x 4 k-chunks
        int buf = cc & 1;
        __syncthreads();
        if (cc < 4 * XT_PER - 1) {
            int nb = buf ^ 1;
            int tn = tbase + ((cc + 1) >> 2);
            int kcn = (cc + 1) & 3;
            const char *xh = (const char *)g_xhi;
            const char *xl = (const char *)g_xlo;
#pragma unroll
            for (int i = 0; i < 8; i++) {
                int idx = tid + i * 128;
                u32 so = (idx >> 4) * 272 + (idx & 15) * 16;
                size_t srco =
                    (((size_t)tn * D_ + kcn * 64 + (idx >> 4)) << 8) + (idx & 15) * 16;
                cpasync16(sb + XS_A + (nb * 2 + 0) * XA_ONE + so, xh + srco);
                cpasync16(sb + XS_A + (nb * 2 + 1) * XA_ONE + so, xl + srco);
            }
            cpcommit(); cpwait1();
        } else {
            cpwait0();
        }
        __syncthreads();

        int kc = cc & 3;
        u32 ahb = sb + XS_A + (buf * 2 + 0) * XA_ONE;
        u32 alb = sb + XS_A + (buf * 2 + 1) * XA_ONE;
#pragma unroll
        for (int kt = 0; kt < 4; kt++) {
            u32 bh[4][4], bl[4][4];
#pragma unroll
            for (int ng = 0; ng < 4; ng++) {
                u32 ba = sb + XS_B + (u32)(ng * (16 * 528)) + b_off
                       + (u32)kc * 128 + kt * 32;
                LDSM4(bh[ng], ba);
                LDSM4(bl[ng], ba + XB_TERM);
            }
#pragma unroll
            for (int i = 0; i < 2; i++) {
                u32 ah[4], al[4];
                u32 aoff = (u32)((kt * 16 + a_row) * 272 + (a_mc + i * 16) * 2);
                LDSM4T(ah, ahb + aoff);
                LDSM4T(al, alb + aoff);
#pragma unroll
                for (int ng = 0; ng < 4; ng++)
#pragma unroll
                    for (int nt = 0; nt < 2; nt++) {
                        MMA(acc[i][ng * 2 + nt], ah, &bh[ng][nt * 2]);
                        MMA(acc[i][ng * 2 + nt], al, &bh[ng][nt * 2]);
                        MMA(acc[i][ng * 2 + nt], ah, &bl[ng][nt * 2]);
                    }
            }
        }

        if (kc == 3) {   // epilogue for this t
            int tcur = tbase + (cc >> 2);
#pragma unroll
            for (int i = 0; i < 2; i++)
#pragma unroll
                for (int n8 = 0; n8 < 8; n8++) {
                    int r = w * 32 + i * 16 + (l >> 2);
                    int ccol = n8 * 8 + (l & 3) * 2;
                    sD[r * 65 + ccol] = acc[i][n8][0];
                    sD[r * 65 + ccol + 1] = acc[i][n8][1];
                    sD[(r + 8) * 65 + ccol] = acc[i][n8][2];
                    sD[(r + 8) * 65 + ccol + 1] = acc[i][n8][3];
                }
            __syncthreads();
            size_t obase = ((size_t)tcur * G4_ + (size_t)cb * 64) * B_;
#pragma unroll
            for (int i = 0; i < 64; i++) {
                int idx = tid + i * 128;
                int n = idx >> 7, b = idx & 127;
                g_xproj[obase + (size_t)n * B_ + b] = sD[b * 65 + n];
            }
            if (cc < 4 * XT_PER - 1) {
#pragma unroll
                for (int i = 0; i < 2; i++)
#pragma unroll
                    for (int n8 = 0; n8 < 8; n8++)
#pragma unroll
                        for (int j = 0; j < 4; j++) acc[i][n8][j] = 0.f;
            }
        }
    }
}

// ---- persistent recurrence: verified R11 (5476us) version, byte-identical ----
__global__ void __launch_bounds__(256, 1) lstm_mma2() {
    extern __shared__ char smraw[];
    u32 sb = (u32)__cvta_generic_to_shared(smraw);
    int tid = threadIdx.x, w = tid >> 5, l = tid & 31;
    int wm = w & 3;              // m-split (m = wm*32..+31)
    int nh = w >> 2;             // n-half (0/1)
    int cta = blockIdx.x;
    float *sD = (float *)(smraw + LD_);
    float *sbe = (float *)(smraw + LBE);
    float *sbr = (float *)(smraw + LBR);

    if (tid < 32) {
        sbe[tid] = g_be2[cta * 32 + tid];
        sbr[tid] = g_braw2[cta * 32 + tid];
    }
    // stage resident R (hi/lo): 32 rows x 1024B each, smem pitch 1040
#pragma unroll
    for (int e = 0; e < 2; e++) {
        const char *src = (const char *)(e ? g_Rlo : g_Rhi) + (size_t)cta * 32 * U_ * 2;
#pragma unroll
        for (int i = 0; i < 8; i++) {
            int idx = tid + i * 256;
            int gr = idx >> 6, gc = idx & 63;
            cpasync16(sb + LR + e * LRT + gr * 1040 + gc * 16, src + (size_t)idx * 16);
        }
    }
    cpcommit(); cpwait0();
    __syncthreads();

    int a_row = ((l & 16) ? 8 : 0) + (l & 7);
    int a_mc  = wm * 32 + ((l & 8) ? 8 : 0);
    int b_off = (nh * 16 + ((l & 16) ? 8 : 0) + (l & 7)) * 1040 + ((l & 8) ? 16 : 0);

    float cst[8];
#pragma unroll
    for (int i = 0; i < 8; i++) cst[i] = 0.f;
    int ph = 0;

    for (int t = 0; t < T_; t++) {
        float xpf[32];
        if (tid < 128) {
#pragma unroll
            for (int n = 0; n < 32; n++)
                xpf[n] = __ldcg(&g_xproj[((size_t)t * G4_ + cta * 32 + n) * B_ + tid]);
        }

        if (t) {
            const char *hhi = (const char *)g_hKhi[ph];
            const char *hlo = (const char *)g_hKlo[ph];
            float acc[2][2][4];
#pragma unroll
            for (int i = 0; i < 2; i++)
#pragma unroll
                for (int nt = 0; nt < 2; nt++)
#pragma unroll
                    for (int j = 0; j < 4; j++) acc[i][nt][j] = 0.f;

            // stage chunk 0 -> buf 0 (chunk = 128 k-rows x 256B, both terms)
#pragma unroll
            for (int e = 0; e < 2; e++) {
                const char *s = e ? hlo : hhi;
#pragma unroll
                for (int i = 0; i < 8; i++) {
                    int idx = tid + i * 256;
                    u32 so = (idx >> 4) * 272 + (idx & 15) * 16;
                    cpasync16(sb + LA + e * LA_T + so, s + (size_t)idx * 16);
                }
            }
            cpcommit();

            for (int ch = 0; ch < 4; ch++) {
                int buf = ch & 1;
                __syncthreads();
                if (ch < 3) {
                    int nb = buf ^ 1;
#pragma unroll
                    for (int e = 0; e < 2; e++) {
                        const char *s = (e ? hlo : hhi) + (size_t)(ch + 1) * 32768;
#pragma unroll
                        for (int i = 0; i < 8; i++) {
                            int idx = tid + i * 256;
                            u32 so = (idx >> 4) * 272 + (idx & 15) * 16;
                            cpasync16(sb + LA + nb * LA_BUF + e * LA_T + so,
                                      s + (size_t)idx * 16);
                        }
                    }
                    cpcommit(); cpwait1();
                } else {
                    cpwait0();
                }
                __syncthreads();

                u32 ahb = sb + LA + buf * LA_BUF;
                u32 alb = ahb + LA_T;
#pragma unroll
                for (int kt = 0; kt < 8; kt++) {
                    u32 bh[4], bl[4];
                    u32 ba = sb + LR + b_off + (u32)ch * 256 + kt * 32;
                    LDSM4(bh, ba);
                    LDSM4(bl, ba + LRT);
#pragma unroll
                    for (int i = 0; i < 2; i++) {
                        u32 ah[4], al[4];
                        u32 aoff = (u32)((kt * 16 + a_row) * 272 + (a_mc + i * 16) * 2);
                        LDSM4T(ah, ahb + aoff);
                        LDSM4T(al, alb + aoff);
#pragma unroll
                        for (int nt = 0; nt < 2; nt++) {
                            MMA(acc[i][nt], ah, &bh[nt * 2]);
                            MMA(acc[i][nt], al, &bh[nt * 2]);
                            MMA(acc[i][nt], ah, &bl[nt * 2]);
                        }
                    }
                }
            }
            // epilogue: write partials (disjoint by n-half)
#pragma unroll
            for (int i = 0; i < 2; i++)
#pragma unroll
                for (int nt = 0; nt < 2; nt++) {
                    int r = wm * 32 + i * 16 + (l >> 2);
                    int cc = nh * 16 + nt * 8 + (l & 3) * 2;
                    *(float2 *)&sD[r * 34 + cc] =
                        make_float2(acc[i][nt][0], acc[i][nt][1]);
                    *(float2 *)&sD[(r + 8) * 34 + cc] =
                        make_float2(acc[i][nt][2], acc[i][nt][3]);
                }
        }
        __syncthreads();

        if (tid < 128) {
            int b = tid;
            float z[32];
            if (t) {
#pragma unroll
                for (int n = 0; n < 32; n++) z[n] = sD[b * 34 + n] + xpf[n] + sbe[n];
            } else {
#pragma unroll
                for (int n = 0; n < 32; n++) z[n] = xpf[n] + sbr[n];
            }
            float hh[8];
#pragma unroll
            for (int ul = 0; ul < 8; ul++) {
                float zi = z[ul * 4 + 0], zf = z[ul * 4 + 1];
                float zg = z[ul * 4 + 2], zo = z[ul * 4 + 3];
                float cn = sigm(zf) * cst[ul] + sigm(zi) * tanh_(zg);
                cst[ul] = cn;
                hh[ul] = sigm(zo) * tanh_(cn);
            }
            {
                float *d = &g_hall[((size_t)b * T_ + t) * U_ + cta * 8];
                *(float4 *)(d + 0) = make_float4(hh[0], hh[1], hh[2], hh[3]);
                *(float4 *)(d + 4) = make_float4(hh[4], hh[5], hh[6], hh[7]);
            }
            int nxt = ph ^ 1;
#pragma unroll
            for (int ul = 0; ul < 8; ul++) {
                __nv_bfloat16 hi = __float2bfloat16(hh[ul]);
                __nv_bfloat16 lo = __float2bfloat16(hh[ul] - __bfloat162float(hi));
                g_hKhi[nxt][(cta * 8 + ul) * B_ + b] = hi;
                g_hKlo[nxt][(cta * 8 + ul) * B_ + b] = lo;
            }
        }
        __threadfence();
        __syncthreads();
        // O(1)-arrival flag barrier (proven R11)
        if (tid == 0) atomicExch(&g_step[cta], (unsigned)(t + 1));
        if (tid < NL) {
            while (*((volatile unsigned *)&g_step[tid]) < (unsigned)(t + 1)) { }
        }
        __syncthreads();
        ph ^= 1;
    }
}

// ---- dense head: Y = H @ dense_w + db ----
__global__ void __launch_bounds__(512) dense_kernel(const float *__restrict__ dw,
                                                    const float *__restrict__ db,
                                                    float *__restrict__ out) {
    __shared__ float sdw[128 * 64];
    __shared__ float sh[16 * 128];
    int tid = threadIdx.x;
    size_t r0 = (size_t)blockIdx.x * 16;
    int o = tid & 63, rr = tid >> 6;
    float a0 = 0.f, a1 = 0.f;
    for (int u0 = 0; u0 < 512; u0 += 128) {
        __syncthreads();
        for (int i = tid; i < 128 * 64; i += 512)
            sdw[i] = dw[(u0 + (i >> 6)) * 64 + (i & 63)];
        for (int i = tid; i < 16 * 128; i += 512)
            sh[i] = g_hall[(r0 + (i >> 7)) * 512 + u0 + (i & 127)];
        __syncthreads();
#pragma unroll 8
        for (int u = 0; u < 128; u++) {
            float wv = sdw[u * 64 + o];
            a0 = fmaf(sh[rr * 128 + u], wv, a0);
            a1 = fmaf(sh[(rr + 8) * 128 + u], wv, a1);
        }
    }
    float bo = db[o];
    out[(r0 + rr) * 64 + o] = a0 + bo;
    out[(r0 + rr + 8) * 64 + o] = a1 + bo;
}

// ---- launch ----
extern "C" void kernel_launch(void *const *d_in, const int *in_sizes, int n_in,
                              void *d_out, int out_size) {
    const float *inputs  = (const float *)d_in[0];
    const float *kernelw = (const float *)d_in[1];
    const float *rec     = (const float *)d_in[2];
    const float *bias    = (const float *)d_in[3];
    const float *dense_w = (const float *)d_in[4];
    const float *dense_b = (const float *)d_in[5];
    float *out = (float *)d_out;
    (void)in_sizes; (void)n_in; (void)out_size;

    cudaFuncSetAttribute(xproj_mma, cudaFuncAttributeMaxDynamicSharedMemorySize, XS_TOT);
    cudaFuncSetAttribute(lstm_mma2, cudaFuncAttributeMaxDynamicSharedMemorySize, L_TOT);

    cvt_k_kernel<<<D_, 256>>>(kernelw);
    cvt_x_kernel<<<dim3(T_, 4), 256>>>(inputs);
    prep_reff_kernel<<<U_, 256>>>(kernelw, rec, dense_w);
    prep_bias_kernel<<<G4_ / 256, 256>>>(kernelw, bias, dense_b);
    zero_flags_kernel<<<1, 64>>>();
    xproj_mma<<<dim3(32, T_ / XT_PER), 128, XS_TOT>>>();
    lstm_mma2<<<NL, 256, L_TOT>>>();
    dense_kernel<<<(B_ * T_) / 16, 512>>>(dense_w, dense_b, out);
}

// round 17
// speedup vs baseline: 1.8894x; 1.0012x over previous
#include <cuda_runtime.h>
#include <cuda_bf16.h>
#include <cstdint>

#define B_ 128
#define T_ 512
#define D_ 256
#define U_ 512
#define G4_ 2048
#define OUT_ 64
#define NL 64                     // lstm CTAs (1/SM, co-resident)

typedef unsigned int u32;

// ---- lstm smem layout (bytes) ----
#define LR     0                  // R resident: 2 terms x 32 rows x 1040B
#define LRT    33280
#define LA     66560              // A bufs: [2 buf][2 term] x (128 rows x 272B)
#define LA_T   34816
#define LA_BUF 69632
#define LD_    205824             // sD: 128 x 34 f32
#define LBE    223232
#define LBR    223360
#define L_TOT  223488

// ---- xproj smem layout ----
#define XB_TERM  33792            // 64 n-rows x 528B
#define XS_B     0
#define XA_ONE   17408
#define XS_A     67584
#define XS_D     137216           // 128 x 65 f32
#define XS_TOT   170496

#define XT_PER   16               // timesteps per xproj CTA

__device__ float g_xproj[(size_t)T_ * G4_ * B_];          // [t][pcol][b]
__device__ float g_hall[(size_t)B_ * T_ * U_];            // [b][t][u]
__device__ __nv_bfloat16 g_Rhi[(size_t)G4_ * U_];         // [pcol][k]
__device__ __nv_bfloat16 g_Rlo[(size_t)G4_ * U_];
__device__ __nv_bfloat16 g_hKhi[2][U_ * B_];              // [k][m] ping-pong
__device__ __nv_bfloat16 g_hKlo[2][U_ * B_];
__device__ __nv_bfloat16 g_xhi[(size_t)T_ * D_ * B_];     // [t][d][b]
__device__ __nv_bfloat16 g_xlo[(size_t)T_ * D_ * B_];
__device__ __nv_bfloat16 g_Khi[(size_t)G4_ * D_];         // [pcol][d]
__device__ __nv_bfloat16 g_Klo[(size_t)G4_ * D_];
__device__ float g_be2[G4_], g_braw2[G4_];
__device__ unsigned g_step[NL];                           // per-CTA step flags

__device__ __forceinline__ float sigm(float x) { return __fdividef(1.f, 1.f + __expf(-x)); }
__device__ __forceinline__ float tanh_(float x) {
    float a = fabsf(x), e = __expf(-2.f * a);
    return copysignf(__fdividef(1.f - e, 1.f + e), x);
}
__device__ __forceinline__ void cpasync16(u32 s, const void *g) {
    asm volatile("cp.async.cg.shared.global [%0], [%1], 16;" :: "r"(s), "l"(g));
}
__device__ __forceinline__ void cpcommit() { asm volatile("cp.async.commit_group;"); }
__device__ __forceinline__ void cpwait0()  { asm volatile("cp.async.wait_group 0;"); }
__device__ __forceinline__ void cpwait1()  { asm volatile("cp.async.wait_group 1;"); }

#define LDSM4(r, a) asm volatile( \
    "ldmatrix.sync.aligned.m8n8.x4.shared.b16 {%0,%1,%2,%3}, [%4];" \
    : "=r"((r)[0]), "=r"((r)[1]), "=r"((r)[2]), "=r"((r)[3]) : "r"(a))
#define LDSM4T(r, a) asm volatile( \
    "ldmatrix.sync.aligned.m8n8.x4.trans.shared.b16 {%0,%1,%2,%3}, [%4];" \
    : "=r"((r)[0]), "=r"((r)[1]), "=r"((r)[2]), "=r"((r)[3]) : "r"(a))
#define MMA(d, a, b) asm volatile( \
    "mma.sync.aligned.m16n8k16.row.col.f32.bf16.bf16.f32 " \
    "{%0,%1,%2,%3}, {%4,%5,%6,%7}, {%8,%9}, {%0,%1,%2,%3};" \
    : "+f"((d)[0]), "+f"((d)[1]), "+f"((d)[2]), "+f"((d)[3]) \
    : "r"((a)[0]), "r"((a)[1]), "r"((a)[2]), "r"((a)[3]), "r"((b)[0]), "r"((b)[1]))

// pcol = (u>>3)*32 + (u&7)*4 + gate
__device__ __forceinline__ int perm_col(int col) {
    int u = col & (U_ - 1), gate = col >> 9;
    return (u >> 3) * 32 + (u & 7) * 4 + gate;
}

// ---- mega prep: cvt_x (blk<2048) | prep_reff (2048..2559) | cvt_k+bias (2560..2815)
__global__ void __launch_bounds__(256) megaprep_kernel(const float *__restrict__ inp,
                                                       const float *__restrict__ wk,
                                                       const float *__restrict__ rec,
                                                       const float *__restrict__ dw,
                                                       const float *__restrict__ bias,
                                                       const float *__restrict__ db) {
    __shared__ float sm[128 * 65];
    int blk = blockIdx.x, tid = threadIdx.x;
    if (blk < 2048) {
        // cvt_x: inputs [b][t][d] f32 -> [t][d][b] bf16 hi/lo
        int t = blk >> 2, d0 = (blk & 3) * 64;
#pragma unroll
        for (int i = 0; i < 32; i++) {
            int idx = tid + i * 256;
            int b = idx >> 6, dl = idx & 63;
            sm[b * 65 + dl] = inp[((size_t)b * T_ + t) * D_ + d0 + dl];
        }
        __syncthreads();
#pragma unroll
        for (int i = 0; i < 32; i++) {
            int idx = tid + i * 256;
            int dl = idx >> 7, b = idx & 127;
            float v = sm[b * 65 + dl];
            __nv_bfloat16 hi = __float2bfloat16(v);
            size_t o = ((size_t)t * D_ + d0 + dl) * B_ + b;
            g_xhi[o] = hi;
            g_xlo[o] = __float2bfloat16(v - __bfloat162float(hi));
        }
    } else if (blk < 2560) {
        // prep_reff: R_eff = rec + dw@Kfb, bf16 hi/lo, [pcol][k]
        int k = blk - 2048;
        if (tid < OUT_) sm[tid] = dw[k * OUT_ + tid];
        __syncthreads();
        for (int col = tid; col < G4_; col += 256) {
            float acc = rec[k * G4_ + col];
#pragma unroll 16
            for (int j = 0; j < OUT_; j++)
                acc += sm[j] * wk[(size_t)(D_ + j) * G4_ + col];
            size_t dst = (size_t)perm_col(col) * U_ + k;
            __nv_bfloat16 hi = __float2bfloat16(acc);
            g_Rhi[dst] = hi;
            g_Rlo[dst] = __float2bfloat16(acc - __bfloat162float(hi));
        }
    } else {
        // cvt_k + (first 8 blocks) bias
        int d = blk - 2560;
        for (int col = tid; col < G4_; col += 256) {
            float v = wk[(size_t)d * G4_ + col];
            __nv_bfloat16 hi = __float2bfloat16(v);
            size_t dst = (size_t)perm_col(col) * D_ + d;
            g_Khi[dst] = hi;
            g_Klo[dst] = __float2bfloat16(v - __bfloat162float(hi));
        }
        if (d < 8) {
            int col = d * 256 + tid;
            float acc = 0.f;
#pragma unroll 16
            for (int j = 0; j < OUT_; j++)
                acc += db[j] * wk[(size_t)(D_ + j) * G4_ + col];
            int pcol = perm_col(col);
            g_braw2[pcol] = bias[col];
            g_be2[pcol] = bias[col] + acc;
        }
    }
}

__global__ void zero_flags_kernel() {
    if (threadIdx.x < NL) g_step[threadIdx.x] = 0;
}

// ---- Xproj on mma.sync bf16 hi/lo: 16 t per CTA (validated R16) ----
__global__ void __launch_bounds__(128, 1) xproj_mma() {
    extern __shared__ char smraw[];
    u32 sb = (u32)__cvta_generic_to_shared(smraw);
    float *sD = (float *)(smraw + XS_D);
    int tid = threadIdx.x, w = tid >> 5, l = tid & 31;
    int cb = blockIdx.x;
    int tbase = blockIdx.y * XT_PER;

    {
        const char *kh = (const char *)g_Khi;
        const char *kl = (const char *)g_Klo;
#pragma unroll
        for (int i = 0; i < 16; i++) {
            int idx = tid + i * 128;
            int gr = idx >> 5, gc = idx & 31;
            u32 dsto = (u32)(gr * 528 + gc * 16);
            size_t srco = (((size_t)cb * 64 + gr) << 9) + gc * 16;
            cpasync16(sb + XS_B + dsto, kh + srco);
            cpasync16(sb + XS_B + XB_TERM + dsto, kl + srco);
        }
        const char *xh = (const char *)g_xhi;
        const char *xl = (const char *)g_xlo;
#pragma unroll
        for (int i = 0; i < 8; i++) {
            int idx = tid + i * 128;
            u32 so = (idx >> 4) * 272 + (idx & 15) * 16;
            size_t srco = (((size_t)tbase * D_ + (idx >> 4)) << 8) + (idx & 15) * 16;
            cpasync16(sb + XS_A + 0 * XA_ONE + so, xh + srco);
            cpasync16(sb + XS_A + 1 * XA_ONE + so, xl + srco);
        }
        cpcommit();
    }

    int a_row = ((l & 16) ? 8 : 0) + (l & 7);
    int a_mc  = w * 32 + ((l & 8) ? 8 : 0);
    int b_off = (((l & 16) ? 8 : 0) + (l & 7)) * 528 + ((l & 8) ? 16 : 0);

    float acc[2][8][4];
#pragma unroll
    for (int i = 0; i < 2; i++)
#pragma unroll
        for (int n8 = 0; n8 < 8; n8++)
#pragma unroll
            for (int j = 0; j < 4; j++) acc[i][n8][j] = 0.f;

    for (int cc = 0; cc < 4 * XT_PER; cc++) {
        int buf = cc & 1;
        __syncthreads();
        if (cc < 4 * XT_PER - 1) {
            int nb = buf ^ 1;
            int tn = tbase + ((cc + 1) >> 2);
            int kcn = (cc + 1) & 3;
            const char *xh = (const char *)g_xhi;
            const char *xl = (const char *)g_xlo;
#pragma unroll
            for (int i = 0; i < 8; i++) {
                int idx = tid + i * 128;
                u32 so = (idx >> 4) * 272 + (idx & 15) * 16;
                size_t srco =
                    (((size_t)tn * D_ + kcn * 64 + (idx >> 4)) << 8) + (idx & 15) * 16;
                cpasync16(sb + XS_A + (nb * 2 + 0) * XA_ONE + so, xh + srco);
                cpasync16(sb + XS_A + (nb * 2 + 1) * XA_ONE + so, xl + srco);
            }
            cpcommit(); cpwait1();
        } else {
            cpwait0();
        }
        __syncthreads();

        int kc = cc & 3;
        u32 ahb = sb + XS_A + (buf * 2 + 0) * XA_ONE;
        u32 alb = sb + XS_A + (buf * 2 + 1) * XA_ONE;
#pragma unroll
        for (int kt = 0; kt < 4; kt++) {
            u32 bh[4][4], bl[4][4];
#pragma unroll
            for (int ng = 0; ng < 4; ng++) {
                u32 ba = sb + XS_B + (u32)(ng * (16 * 528)) + b_off
                       + (u32)kc * 128 + kt * 32;
                LDSM4(bh[ng], ba);
                LDSM4(bl[ng], ba + XB_TERM);
            }
#pragma unroll
            for (int i = 0; i < 2; i++) {
                u32 ah[4], al[4];
                u32 aoff = (u32)((kt * 16 + a_row) * 272 + (a_mc + i * 16) * 2);
                LDSM4T(ah, ahb + aoff);
                LDSM4T(al, alb + aoff);
#pragma unroll
                for (int ng = 0; ng < 4; ng++)
#pragma unroll
                    for (int nt = 0; nt < 2; nt++) {
                        MMA(acc[i][ng * 2 + nt], ah, &bh[ng][nt * 2]);
                        MMA(acc[i][ng * 2 + nt], al, &bh[ng][nt * 2]);
                        MMA(acc[i][ng * 2 + nt], ah, &bl[ng][nt * 2]);
                    }
            }
        }

        if (kc == 3) {
            int tcur = tbase + (cc >> 2);
#pragma unroll
            for (int i = 0; i < 2; i++)
#pragma unroll
                for (int n8 = 0; n8 < 8; n8++) {
                    int r = w * 32 + i * 16 + (l >> 2);
                    int ccol = n8 * 8 + (l & 3) * 2;
                    sD[r * 65 + ccol] = acc[i][n8][0];
                    sD[r * 65 + ccol + 1] = acc[i][n8][1];
                    sD[(r + 8) * 65 + ccol] = acc[i][n8][2];
                    sD[(r + 8) * 65 + ccol + 1] = acc[i][n8][3];
                }
            __syncthreads();
            size_t obase = ((size_t)tcur * G4_ + (size_t)cb * 64) * B_;
#pragma unroll
            for (int i = 0; i < 64; i++) {
                int idx = tid + i * 128;
                int n = idx >> 7, b = idx & 127;
                g_xproj[obase + (size_t)n * B_ + b] = sD[b * 65 + n];
            }
            if (cc < 4 * XT_PER - 1) {
#pragma unroll
                for (int i = 0; i < 2; i++)
#pragma unroll
                    for (int n8 = 0; n8 < 8; n8++)
#pragma unroll
                        for (int j = 0; j < 4; j++) acc[i][n8][j] = 0.f;
            }
        }
    }
}

// ---- persistent recurrence (R11 skeleton; chunk0 staged before xpf loads) ----
__global__ void __launch_bounds__(256, 1) lstm_mma2() {
    extern __shared__ char smraw[];
    u32 sb = (u32)__cvta_generic_to_shared(smraw);
    int tid = threadIdx.x, w = tid >> 5, l = tid & 31;
    int wm = w & 3;
    int nh = w >> 2;
    int cta = blockIdx.x;
    float *sD = (float *)(smraw + LD_);
    float *sbe = (float *)(smraw + LBE);
    float *sbr = (float *)(smraw + LBR);

    if (tid < 32) {
        sbe[tid] = g_be2[cta * 32 + tid];
        sbr[tid] = g_braw2[cta * 32 + tid];
    }
#pragma unroll
    for (int e = 0; e < 2; e++) {
        const char *src = (const char *)(e ? g_Rlo : g_Rhi) + (size_t)cta * 32 * U_ * 2;
#pragma unroll
        for (int i = 0; i < 8; i++) {
            int idx = tid + i * 256;
            int gr = idx >> 6, gc = idx & 63;
            cpasync16(sb + LR + e * LRT + gr * 1040 + gc * 16, src + (size_t)idx * 16);
        }
    }
    cpcommit(); cpwait0();
    __syncthreads();

    int a_row = ((l & 16) ? 8 : 0) + (l & 7);
    int a_mc  = wm * 32 + ((l & 8) ? 8 : 0);
    int b_off = (nh * 16 + ((l & 16) ? 8 : 0) + (l & 7)) * 1040 + ((l & 8) ? 16 : 0);

    float cst[8];
#pragma unroll
    for (int i = 0; i < 8; i++) cst[i] = 0.f;
    int ph = 0;

    for (int t = 0; t < T_; t++) {
        const char *hhi = (const char *)g_hKhi[ph];
        const char *hlo = (const char *)g_hKlo[ph];

        // kick chunk-0 h staging FIRST (critical L2 chain starts immediately)
        if (t) {
#pragma unroll
            for (int e = 0; e < 2; e++) {
                const char *s = e ? hlo : hhi;
#pragma unroll
                for (int i = 0; i < 8; i++) {
                    int idx = tid + i * 256;
                    u32 so = (idx >> 4) * 272 + (idx & 15) * 16;
                    cpasync16(sb + LA + e * LA_T + so, s + (size_t)idx * 16);
                }
            }
            cpcommit();
        }

        // xpf DRAM loads overlap chunk-0 staging
        float xpf[32];
        if (tid < 128) {
#pragma unroll
            for (int n = 0; n < 32; n++)
                xpf[n] = __ldcg(&g_xproj[((size_t)t * G4_ + cta * 32 + n) * B_ + tid]);
        }

        if (t) {
            float acc[2][2][4];
#pragma unroll
            for (int i = 0; i < 2; i++)
#pragma unroll
                for (int nt = 0; nt < 2; nt++)
#pragma unroll
                    for (int j = 0; j < 4; j++) acc[i][nt][j] = 0.f;

            for (int ch = 0; ch < 4; ch++) {
                int buf = ch & 1;
                __syncthreads();
                if (ch < 3) {
                    int nb = buf ^ 1;
#pragma unroll
                    for (int e = 0; e < 2; e++) {
                        const char *s = (e ? hlo : hhi) + (size_t)(ch + 1) * 32768;
#pragma unroll
                        for (int i = 0; i < 8; i++) {
                            int idx = tid + i * 256;
                            u32 so = (idx >> 4) * 272 + (idx & 15) * 16;
                            cpasync16(sb + LA + nb * LA_BUF + e * LA_T + so,
                                      s + (size_t)idx * 16);
                        }
                    }
                    cpcommit(); cpwait1();
                } else {
                    cpwait0();
                }
                __syncthreads();

                u32 ahb = sb + LA + buf * LA_BUF;
                u32 alb = ahb + LA_T;
#pragma unroll
                for (int kt = 0; kt < 8; kt++) {
                    u32 bh[4], bl[4];
                    u32 ba = sb + LR + b_off + (u32)ch * 256 + kt * 32;
                    LDSM4(bh, ba);
                    LDSM4(bl, ba + LRT);
#pragma unroll
                    for (int i = 0; i < 2; i++) {
                        u32 ah[4], al[4];
                        u32 aoff = (u32)((kt * 16 + a_row) * 272 + (a_mc + i * 16) * 2);
                        LDSM4T(ah, ahb + aoff);
                        LDSM4T(al, alb + aoff);
#pragma unroll
                        for (int nt = 0; nt < 2; nt++) {
                            MMA(acc[i][nt], ah, &bh[nt * 2]);
                            MMA(acc[i][nt], al, &bh[nt * 2]);
                            MMA(acc[i][nt], ah, &bl[nt * 2]);
                        }
                    }
                }
            }
#pragma unroll
            for (int i = 0; i < 2; i++)
#pragma unroll
                for (int nt = 0; nt < 2; nt++) {
                    int r = wm * 32 + i * 16 + (l >> 2);
                    int cc = nh * 16 + nt * 8 + (l & 3) * 2;
                    *(float2 *)&sD[r * 34 + cc] =
                        make_float2(acc[i][nt][0], acc[i][nt][1]);
                    *(float2 *)&sD[(r + 8) * 34 + cc] =
                        make_float2(acc[i][nt][2], acc[i][nt][3]);
                }
        }
        __syncthreads();

        if (tid < 128) {
            int b = tid;
            float z[32];
            if (t) {
#pragma unroll
                for (int n = 0; n < 32; n++) z[n] = sD[b * 34 + n] + xpf[n] + sbe[n];
            } else {
#pragma unroll
                for (int n = 0; n < 32; n++) z[n] = xpf[n] + sbr[n];
            }
            float hh[8];
#pragma unroll
            for (int ul = 0; ul < 8; ul++) {
                float zi = z[ul * 4 + 0], zf = z[ul * 4 + 1];
                float zg = z[ul * 4 + 2], zo = z[ul * 4 + 3];
                float cn = sigm(zf) * cst[ul] + sigm(zi) * tanh_(zg);
                cst[ul] = cn;
                hh[ul] = sigm(zo) * tanh_(cn);
            }
            {
                float *d = &g_hall[((size_t)b * T_ + t) * U_ + cta * 8];
                *(float4 *)(d + 0) = make_float4(hh[0], hh[1], hh[2], hh[3]);
                *(float4 *)(d + 4) = make_float4(hh[4], hh[5], hh[6], hh[7]);
            }
            int nxt = ph ^ 1;
#pragma unroll
            for (int ul = 0; ul < 8; ul++) {
                __nv_bfloat16 hi = __float2bfloat16(hh[ul]);
                __nv_bfloat16 lo = __float2bfloat16(hh[ul] - __bfloat162float(hi));
                g_hKhi[nxt][(cta * 8 + ul) * B_ + b] = hi;
                g_hKlo[nxt][(cta * 8 + ul) * B_ + b] = lo;
            }
            __threadfence();     // only the storing threads fence
        }
        __syncthreads();
        if (tid == 0) atomicExch(&g_step[cta], (unsigned)(t + 1));
        if (tid < NL) {
            while (*((volatile unsigned *)&g_step[tid]) < (unsigned)(t + 1)) { }
        }
        __syncthreads();
        ph ^= 1;
    }
}

// ---- dense head: Y = H @ dense_w + db ----
__global__ void __launch_bounds__(512) dense_kernel(const float *__restrict__ dw,
                                                    const float *__restrict__ db,
                                                    float *__restrict__ out) {
    __shared__ float sdw[128 * 64];
    __shared__ float sh[16 * 128];
    int tid = threadIdx.x;
    size_t r0 = (size_t)blockIdx.x * 16;
    int o = tid & 63, rr = tid >> 6;
    float a0 = 0.f, a1 = 0.f;
    for (int u0 = 0; u0 < 512; u0 += 128) {
        __syncthreads();
        for (int i = tid; i < 128 * 64; i += 512)
            sdw[i] = dw[(u0 + (i >> 6)) * 64 + (i & 63)];
        for (int i = tid; i < 16 * 128; i += 512)
            sh[i] = g_hall[(r0 + (i >> 7)) * 512 + u0 + (i & 127)];
        __syncthreads();
#pragma unroll 8
        for (int u = 0; u < 128; u++) {
            float wv = sdw[u * 64 + o];
            a0 = fmaf(sh[rr * 128 + u], wv, a0);
            a1 = fmaf(sh[(rr + 8) * 128 + u], wv, a1);
        }
    }
    float bo = db[o];
    out[(r0 + rr) * 64 + o] = a0 + bo;
    out[(r0 + rr + 8) * 64 + o] = a1 + bo;
}

// ---- launch: lstm is the 4th kernel in the stream ----
extern "C" void kernel_launch(void *const *d_in, const int *in_sizes, int n_in,
                              void *d_out, int out_size) {
    const float *inputs  = (const float *)d_in[0];
    const float *kernelw = (const float *)d_in[1];
    const float *rec     = (const float *)d_in[2];
    const float *bias    = (const float *)d_in[3];
    const float *dense_w = (const float *)d_in[4];
    const float *dense_b = (const float *)d_in[5];
    float *out = (float *)d_out;
    (void)in_sizes; (void)n_in; (void)out_size;

    cudaFuncSetAttribute(xproj_mma, cudaFuncAttributeMaxDynamicSharedMemorySize, XS_TOT);
    cudaFuncSetAttribute(lstm_mma2, cudaFuncAttributeMaxDynamicSharedMemorySize, L_TOT);

    megaprep_kernel<<<2816, 256>>>(inputs, kernelw, rec, dense_w, bias, dense_b); // 1
    xproj_mma<<<dim3(32, T_ / XT_PER), 128, XS_TOT>>>();                          // 2
    zero_flags_kernel<<<1, 64>>>();                                               // 3
    lstm_mma2<<<NL, 256, L_TOT>>>();                                              // 4
    dense_kernel<<<(B_ * T_) / 16, 512>>>(dense_w, dense_b, out);                 // 5
}